// round 2
// baseline (speedup 1.0000x reference)
#include <cuda_runtime.h>
#include <math.h>

#define B_   64
#define C_   8
#define N_   112
#define LD   113
#define KS   7
#define HALO 3
#define NMAT (B_*C_)
#define TOTAL (B_*C_*N_*N_)
#define MAXTAPS (C_*C_*KS*KS)

// Scratch (static device memory: allowed; no allocation)
__device__ float g_v1[TOTAL];
__device__ int   g_tapkey[MAXTAPS];
__device__ float g_tapw[MAXTAPS];
__device__ int   g_ntaps;

// ---------------------------------------------------------------------------
// Kernel 0: build compacted nonzero-tap list from the conv weight.
// Deterministic: warp 0 scans in index order using ballot-prefix compaction.
// ---------------------------------------------------------------------------
__global__ __launch_bounds__(128)
void build_taps_kernel(const float* __restrict__ w) {
    __shared__ float sw[MAXTAPS];
    for (int i = threadIdx.x; i < MAXTAPS; i += blockDim.x) sw[i] = w[i];
    __syncthreads();
    if (threadIdx.x < 32) {
        const int lane = threadIdx.x;
        int cnt = 0;
        for (int base = 0; base < MAXTAPS; base += 32) {
            int idx = base + lane;
            float val = (idx < MAXTAPS) ? sw[idx] : 0.0f;
            unsigned m = __ballot_sync(0xffffffffu, val != 0.0f);
            if (val != 0.0f) {
                int pos = cnt + __popc(m & ((1u << lane) - 1u));
                int kj = idx % KS;
                int ki = (idx / KS) % KS;
                int ci = (idx / (KS * KS)) % C_;
                int co = idx / (KS * KS * C_);
                g_tapkey[pos] = (co << 24) | (ci << 16) | (ki << 8) | kj;
                g_tapw[pos] = val;
            }
            cnt += __popc(m);
        }
        if (lane == 0) g_ntaps = cnt;
    }
}

// ---------------------------------------------------------------------------
// Kernel 1: sparse conv  v1 = conv(x1, w) + bias, using the tap list.
// ---------------------------------------------------------------------------
__global__ __launch_bounds__(256)
void conv_kernel(const float* __restrict__ x,
                 const float* __restrict__ bias) {
    int idx = blockIdx.x * blockDim.x + threadIdx.x;
    if (idx >= TOTAL) return;
    int j = idx % N_;
    int i = (idx / N_) % N_;
    int c = (idx / (N_ * N_)) % C_;
    int b = idx / (N_ * N_ * C_);
    float acc = __ldg(&bias[c]);
    const int nt = g_ntaps;
    for (int t = 0; t < nt; ++t) {
        const int key = g_tapkey[t];
        const int co = key >> 24;
        if (co != c) continue;
        const int ci = (key >> 16) & 255;
        const int ki = (key >> 8) & 255;
        const int kj = key & 255;
        const int ii = i + ki - HALO;
        const int jj = j + kj - HALO;
        if (ii >= 0 && ii < N_ && jj >= 0 && jj < N_)
            acc += g_tapw[t] * __ldg(&x[((b * C_ + ci) * N_ + ii) * N_ + jj]);
    }
    g_v1[idx] = acc;
}

// ---------------------------------------------------------------------------
// Kernel 2: per-matrix solver. One CTA per (b,c) matrix.
//   1. load A into shared L (padded LD=113 -> conflict-free column access)
//   2. in-place right-looking Cholesky, rdiag[i] = 1/L[i][i]
//   3. Vi = L^{-1} (thread-per-column forward substitution, unrolled dots)
//   4. Ainv = Vi^T Vi on symmetric pairs (i<=j) fused with final elementwise:
//      out[i,j] = A[i,j] * (Ainv[i,j]/L[i,i] + 1)^2
// ---------------------------------------------------------------------------
extern __shared__ float smem[];

__global__ __launch_bounds__(128, 2)
void solver_kernel(float* __restrict__ out) {
    float* L  = smem;                   // N_ * LD
    float* Vi = smem + N_ * LD;         // N_ * LD
    float* rdiag = smem + 2 * N_ * LD;  // N_

    const int m = blockIdx.x;
    const float* __restrict__ A = g_v1 + (size_t)m * (N_ * N_);
    float* __restrict__ O = out + (size_t)m * (N_ * N_);
    const int T = blockDim.x;
    const int tid = threadIdx.x;

    // ---- load ----
    for (int p = tid; p < N_ * N_; p += T) {
        int i = p / N_;
        int j = p - i * N_;
        L[i * LD + j] = A[p];
    }
    __syncthreads();

    // ---- Cholesky (right-looking) ----
    for (int j = 0; j < N_; ++j) {
        if (tid == 0) {
            float d = sqrtf(L[j * LD + j]);
            L[j * LD + j] = d;
            rdiag[j] = 1.0f / d;
        }
        __syncthreads();
        const float rd = rdiag[j];
        for (int i = j + 1 + tid; i < N_; i += T)
            L[i * LD + j] *= rd;
        __syncthreads();
        for (int i = j + 1 + tid; i < N_; i += T) {
            const float lij = L[i * LD + j];
            int k = j + 1;
            for (; k + 3 <= i; k += 4) {
                L[i * LD + k]     -= lij * L[k * LD + j];
                L[i * LD + k + 1] -= lij * L[(k + 1) * LD + j];
                L[i * LD + k + 2] -= lij * L[(k + 2) * LD + j];
                L[i * LD + k + 3] -= lij * L[(k + 3) * LD + j];
            }
            for (; k <= i; ++k)
                L[i * LD + k] -= lij * L[k * LD + j];
        }
        __syncthreads();
    }

    // ---- triangular inverse Vi = L^{-1}, thread-per-column ----
    if (tid < N_) {
        const int j = tid;
        Vi[j * LD + j] = rdiag[j];
        for (int i = j + 1; i < N_; ++i) {
            float s0 = 0.f, s1 = 0.f, s2 = 0.f, s3 = 0.f;
            int k = j;
            for (; k + 3 < i; k += 4) {
                s0 += L[i * LD + k]       * Vi[k * LD + j];
                s1 += L[i * LD + k + 1]   * Vi[(k + 1) * LD + j];
                s2 += L[i * LD + k + 2]   * Vi[(k + 2) * LD + j];
                s3 += L[i * LD + k + 3]   * Vi[(k + 3) * LD + j];
            }
            float s = (s0 + s1) + (s2 + s3);
            for (; k < i; ++k)
                s += L[i * LD + k] * Vi[k * LD + j];
            Vi[i * LD + j] = -s * rdiag[i];
        }
    }
    __syncthreads();

    // ---- SYRK (Ainv = Vi^T Vi, i<=j) + final elementwise ----
    const int NP = N_ * (N_ + 1) / 2;
    int i = 0;
    int q = tid;
    while (q >= N_ - i) { q -= N_ - i; ++i; }
    for (int p = tid; p < NP; p += T) {
        const int j = i + q;
        float s0 = 0.f, s1 = 0.f, s2 = 0.f, s3 = 0.f;
        int k = j;
        for (; k + 3 < N_; k += 4) {
            s0 += Vi[k * LD + i]       * Vi[k * LD + j];
            s1 += Vi[(k + 1) * LD + i] * Vi[(k + 1) * LD + j];
            s2 += Vi[(k + 2) * LD + i] * Vi[(k + 2) * LD + j];
            s3 += Vi[(k + 3) * LD + i] * Vi[(k + 3) * LD + j];
        }
        float ainv = (s0 + s1) + (s2 + s3);
        for (; k < N_; ++k)
            ainv += Vi[k * LD + i] * Vi[k * LD + j];
        const float aij = A[i * N_ + j];
        const float aji = A[j * N_ + i];
        const float u = ainv * rdiag[i] + 1.0f;
        const float v = ainv * rdiag[j] + 1.0f;
        O[i * N_ + j] = aij * u * u;
        O[j * N_ + i] = aji * v * v;
        q += T;
        while (i < N_ && q >= N_ - i) { q -= N_ - i; ++i; }
    }
}

// ---------------------------------------------------------------------------
extern "C" void kernel_launch(void* const* d_in, const int* in_sizes, int n_in,
                              void* d_out, int out_size) {
    const float* x1   = (const float*)d_in[0];
    const float* w    = (const float*)d_in[1];
    const float* bias = (const float*)d_in[2];
    float* out = (float*)d_out;

    (void)in_sizes; (void)n_in; (void)out_size;

    static const int SMEM_BYTES = (2 * N_ * LD + N_) * (int)sizeof(float);
    cudaFuncSetAttribute(solver_kernel,
                         cudaFuncAttributeMaxDynamicSharedMemorySize,
                         SMEM_BYTES);

    build_taps_kernel<<<1, 128>>>(w);
    conv_kernel<<<(TOTAL + 255) / 256, 256>>>(x1, bias);
    solver_kernel<<<NMAT, 128, SMEM_BYTES>>>(out);
}

// round 5
// speedup vs baseline: 1.2404x; 1.2404x over previous
#include <cuda_runtime.h>
#include <math.h>

#define B_   64
#define C_   8
#define N_   112
#define LD   113
#define KS   7
#define HALO 3
#define NMAT (B_*C_)
#define NPIX (N_*N_)
#define NTRI (N_*(N_+1)/2)     /* 6328 lower-triangle elements (incl diag) */
#define T_   256
#define WPC  (C_*KS*KS)        /* 392 weights per output channel */

// ---------------------------------------------------------------------------
// Fully fused kernel: one CTA per (b,c) 112x112 SPD matrix.
//   Phase 0: per-block sparse-tap compaction of conv weights (warp 0, ballot)
//   Phase 1: conv -> v1 tile into shared (AO full, AS lower copy)
//   Phase 2: 112 symmetric sweep steps on AS lower triangle.
//            After sweeping all pivots: AS = -A^{-1} (lower), and the pivot
//            at step p equals L[p,p]^2  ->  rdiag[p] = rsqrt(pivot).
//   Phase 3: out[i,j] = v1[i,j] * (Ainv[i,j]*rdiag[i] + 1)^2  (both mirrors)
// ---------------------------------------------------------------------------
extern __shared__ float smem[];

__global__ __launch_bounds__(T_, 2)
void fused_kernel(const float* __restrict__ x,
                  const float* __restrict__ w,
                  const float* __restrict__ bias,
                  float* __restrict__ out) {
    float* AS    = smem;                 // N_*LD, lower triangle used
    float* AO    = AS + N_ * LD;         // N_*LD, full (original v1)
    float* cvec  = AO + N_ * LD;         // 128 (padded; only N_ used)
    float* rdiag = cvec + 128;           // 128 (padded)
    float* scal  = rdiag + 128;          // [0] = 1/pivot
    float* twv   = scal + 4;             // WPC tap weights
    int*   tkey  = (int*)(twv + WPC);    // WPC tap keys
    __shared__ int s_ntap;

    const int m   = blockIdx.x;
    const int b   = m / C_;
    const int c   = m % C_;
    const int tid = threadIdx.x;

    // ---- Phase 0: compact nonzero taps of this output channel (warp 0) ----
    if (tid < 32) {
        int cnt = 0;
        for (int base = 0; base < WPC; base += 32) {
            const int idx = base + tid;
            const float val = (idx < WPC) ? __ldg(&w[c * WPC + idx]) : 0.0f;
            const unsigned msk = __ballot_sync(0xffffffffu, val != 0.0f);
            if (val != 0.0f) {
                const int pos = cnt + __popc(msk & ((1u << tid) - 1u));
                const int ci = idx / (KS * KS);
                const int r  = idx % (KS * KS);
                twv[pos]  = val;
                tkey[pos] = (ci << 16) | ((r / KS) << 8) | (r % KS);
            }
            cnt += __popc(msk);
        }
        if (tid == 0) s_ntap = cnt;
    }
    __syncthreads();

    // ---- Phase 1: conv -> shared ----
    {
        const float bc = __ldg(&bias[c]);
        const int nt = s_ntap;
        const float* __restrict__ xb = x + (size_t)b * C_ * NPIX;
        for (int p = tid; p < NPIX; p += T_) {
            const int i = p / N_;
            const int j = p - i * N_;
            float acc = bc;
            for (int t = 0; t < nt; ++t) {
                const int key = tkey[t];
                const int ci = key >> 16;
                const int ki = (key >> 8) & 255;
                const int kj = key & 255;
                const int ii = i + ki - HALO;
                const int jj = j + kj - HALO;
                if (ii >= 0 && ii < N_ && jj >= 0 && jj < N_)
                    acc += twv[t] * __ldg(&xb[(ci * N_ + ii) * N_ + jj]);
            }
            AO[i * LD + j] = acc;
            if (i >= j) AS[i * LD + j] = acc;
        }
    }
    __syncthreads();

    // ---- per-thread contiguous chunk of the flattened lower triangle ----
    const int f0 = (tid * NTRI) >> 8;
    const int f1 = ((tid + 1) * NTRI) >> 8;
    int i0 = (int)((sqrtf(8.0f * (float)f0 + 1.0f) - 1.0f) * 0.5f);
    while ((i0 + 1) * (i0 + 2) / 2 <= f0) ++i0;
    while (i0 * (i0 + 1) / 2 > f0) --i0;
    const int j0 = f0 - i0 * (i0 + 1) / 2;

    // ---- Phase 2: symmetric sweep, 112 pivots ----
    for (int p = 0; p < N_; ++p) {
        if (tid < N_) {
            const float v = (tid >= p) ? AS[tid * LD + p] : AS[p * LD + tid];
            cvec[tid] = v;
            if (tid == p) {
                scal[0]  = 1.0f / v;
                rdiag[p] = rsqrtf(v);
            }
        }
        __syncthreads();
        const float rd = scal[0];
        int i = i0, j = j0;
        float ci   = cvec[i];
        float cird = ci * rd;
        bool  rowp = (i == p);
        #pragma unroll 4
        for (int f = f0; f < f1; ++f) {
            const float a  = AS[i * LD + j];
            const float cj = cvec[j];
            float v = fmaf(-cird, cj, a);
            if (rowp)        v = (j == p) ? -rd : cj * rd;
            else if (j == p) v = cird;
            AS[i * LD + j] = v;
            if (++j > i) {               // next row (cvec padded; safe at end)
                j = 0;
                ++i;
                ci = cvec[i];
                cird = ci * rd;
                rowp = (i == p);
            }
        }
        __syncthreads();
    }

    // ---- Phase 3: fused elementwise output (both mirrors per pair) ----
    {
        float* __restrict__ O = out + (size_t)m * NPIX;
        int i = i0, j = j0;
        for (int f = f0; f < f1; ++f) {
            const float ainv = -AS[i * LD + j];      // A^{-1}[i][j], i>=j
            const float ri = rdiag[i];
            const float rj = rdiag[j];
            const float alo = AO[i * LD + j];
            const float ahi = AO[j * LD + i];
            const float u = fmaf(ainv, ri, 1.0f);
            const float v = fmaf(ainv, rj, 1.0f);
            O[i * N_ + j] = alo * u * u;
            O[j * N_ + i] = ahi * v * v;
            if (++j > i) { j = 0; ++i; }
        }
    }
}

// ---------------------------------------------------------------------------
extern "C" void kernel_launch(void* const* d_in, const int* in_sizes, int n_in,
                              void* d_out, int out_size) {
    const float* x1   = (const float*)d_in[0];
    const float* w    = (const float*)d_in[1];
    const float* bias = (const float*)d_in[2];
    float* out = (float*)d_out;
    (void)in_sizes; (void)n_in; (void)out_size;

    static const int SMEM_BYTES =
        (int)((2 * N_ * LD + 128 + 128 + 4 + WPC) * sizeof(float)
              + WPC * sizeof(int));

    cudaFuncSetAttribute(fused_kernel,
                         cudaFuncAttributeMaxDynamicSharedMemorySize,
                         SMEM_BYTES);

    fused_kernel<<<NMAT, T_, SMEM_BYTES>>>(x1, w, bias, out);
}